// round 14
// baseline (speedup 1.0000x reference)
#include <cuda_runtime.h>
#include <cuda_bf16.h>
#include <cstdint>

// Problem constants
#define NN    20000
#define EE    320000
#define NPAD  20096        // 157 * 128
#define OUTW  208          // 16 + 3*64

#define SWZ128(b) ((b) ^ (((b) >> 3) & 0x70))

// ---- warp-level tensor core primitives (arch-generic PTX, compiles for sm_103) ----
#define LDSM4(r0, r1, r2, r3, addr) \
    asm volatile("ldmatrix.sync.aligned.m8n8.x4.shared.b16 {%0,%1,%2,%3}, [%4];" \
        : "=r"(r0), "=r"(r1), "=r"(r2), "=r"(r3) : "r"(addr))

#define MMA16816(d, a0, a1, a2, a3, b0, b1) \
    asm volatile("mma.sync.aligned.m16n8k16.row.col.f32.bf16.bf16.f32 " \
        "{%0,%1,%2,%3}, {%4,%5,%6,%7}, {%8,%9}, {%0,%1,%2,%3};" \
        : "+f"((d)[0]), "+f"((d)[1]), "+f"((d)[2]), "+f"((d)[3]) \
        : "r"(a0), "r"(a1), "r"(a2), "r"(a3), "r"(b0), "r"(b1))

__device__ __forceinline__ uint32_t smem_u32(const void* p) {
    uint32_t a;
    asm("{ .reg .u64 t; cvta.to.shared.u64 t, %1; cvt.u32.u64 %0, t; }"
        : "=r"(a) : "l"(p));
    return a;
}

// packed bf16x2 convert: lo half = x, hi half = y
__device__ __forceinline__ uint32_t cvt_bf2(float x, float y) {
    uint32_t r;
    asm("cvt.rn.bf16x2.f32 %0, %1, %2;" : "=r"(r) : "f"(y), "f"(x));
    return r;
}
__device__ __forceinline__ void split2(float x, float y, uint32_t& h, uint32_t& l) {
    h = cvt_bf2(x, y);
    float hx = __uint_as_float(h << 16);
    float hy = __uint_as_float(h & 0xffff0000u);
    l = cvt_bf2(x - hx, y - hy);
}

// ---------------- scratch (device globals; no allocation) ----------------
__device__ float g_feat[NPAD * 64];
__device__ float g_cat[NPAD * 768];          // [f_ni | f_nj | hn]
__device__ float g_elog[EE * 4];             // PERM order
__device__ float g_agg[NPAD * 256];
__device__ int   g_off[NN + 1];
__device__ int   g_cursor[NN];
__device__ int   g_perm[EE];
__device__ int   g_psrc[EE];
__device__ int   g_pdst[EE];
__device__ __nv_bfloat16 g_ehi[EE * 64];
__device__ __nv_bfloat16 g_elo[EE * 64];
// W^T blobs: [layer][mat: fij,ni,nj,node][hi/lo] each 256x64 swizzled
__device__ __nv_bfloat16 g_wb[2 * 4 * 2 * 16384];
// W_mlp^T blobs: [layer][kchunk 0..3][hi/lo] each 64 rows x 64 K swizzled
__device__ __nv_bfloat16 g_wmlp[2 * 4 * 2 * 4096];

// ---------------- CSR build ----------------
__global__ void k_zero_cursor() {
    int i = blockIdx.x * blockDim.x + threadIdx.x;
    if (i < NN) g_cursor[i] = 0;
}
__global__ void k_degree(const int* __restrict__ dst) {
    int e = blockIdx.x * blockDim.x + threadIdx.x;
    if (e < EE) atomicAdd(&g_cursor[dst[e]], 1);
}
// scan writes g_off (inclusive, shifted) AND g_cursor (exclusive prefix)
__global__ void k_scan() {
    __shared__ int s[1024];
    __shared__ int carry;
    int t = threadIdx.x;
    if (t == 0) { carry = 0; g_off[0] = 0; }
    __syncthreads();
    for (int base = 0; base < NN; base += 1024) {
        int x = (base + t < NN) ? g_cursor[base + t] : 0;
        s[t] = x;
        __syncthreads();
        for (int d = 1; d < 1024; d <<= 1) {
            int v = (t >= d) ? s[t - d] : 0;
            __syncthreads();
            s[t] += v;
            __syncthreads();
        }
        if (base + t < NN) {
            int inc = carry + s[t];
            g_off[base + t + 1] = inc;
            g_cursor[base + t] = inc - x;   // exclusive prefix for scatter
        }
        __syncthreads();
        if (t == 0) carry += s[1023];
        __syncthreads();
    }
}
__global__ void k_scatter(const int* __restrict__ src, const int* __restrict__ dst) {
    int e = blockIdx.x * blockDim.x + threadIdx.x;
    if (e < EE) {
        int d = dst[e];
        int p = atomicAdd(&g_cursor[d], 1);
        g_perm[p] = e;
        g_psrc[p] = src[e];
        g_pdst[p] = d;
    }
}

// ---------------- embed (+ raw feature copy, cols 0..15) ----------------
__global__ void k_embed(const float* __restrict__ nf,
                        const float* __restrict__ W, const float* __restrict__ b,
                        float* __restrict__ out) {
    __shared__ float sW[16 * 64];
    int tid = threadIdx.x;
#pragma unroll
    for (int i = 0; i < 4; i++) sW[tid + i * 256] = W[tid + i * 256];
    __syncthreads();
    int n = blockIdx.x * 4 + (tid >> 6);
    int c = tid & 63;
    if (n < NN) {
        float acc = b[c];
        const float* r = nf + n * 16;
#pragma unroll
        for (int k = 0; k < 16; k++) acc += r[k] * sW[k * 64 + c];
        g_feat[n * 64 + c] = acc;
        out[n * OUTW + 16 + c] = acc;
        if (c < 16) out[n * OUTW + c] = r[c];   // raw node features
    }
}

// ---------------- prep: edge_feat bf16 split, pre-swizzled, PERM order ----------------
__global__ void k_prep_edge(const float* __restrict__ ef) {
    int idx = blockIdx.x * 256 + threadIdx.x;
    if (idx >= EE * 8) return;
    int p = idx >> 3, q = idx & 7;
    int e = g_perm[p];
    const float* ep = ef + (size_t)e * 64 + q * 8;
    float4 a = *reinterpret_cast<const float4*>(ep);
    float4 b = *reinterpret_cast<const float4*>(ep + 4);
    uint4 H, L;
    split2(a.x, a.y, H.x, L.x);
    split2(a.z, a.w, H.y, L.y);
    split2(b.x, b.y, H.z, L.z);
    split2(b.z, b.w, H.w, L.w);
    unsigned sw = SWZ128((unsigned)((p & 127) * 128 + q * 16));
    size_t byte_base = (size_t)(p >> 7) * 16384;
    *reinterpret_cast<uint4*>(reinterpret_cast<char*>(g_ehi) + byte_base + sw) = H;
    *reinterpret_cast<uint4*>(reinterpret_cast<char*>(g_elo) + byte_base + sw) = L;
}

// ---------------- prep: W^T blobs (fij, ni, nj, node) ----------------
__global__ void k_prepw(const float* __restrict__ Wfij, const float* __restrict__ Wni,
                        const float* __restrict__ Wnj, const float* __restrict__ Wnode) {
    int idx = blockIdx.x * 256 + threadIdx.x;   // 131072
    if (idx >= 131072) return;
    int Lr = idx >> 16;
    int rem = idx & 65535;
    int mat = rem >> 14;
    int t = rem & 16383;
    int r = t >> 6, c = t & 63;
    const float* W = (mat == 0) ? Wfij : (mat == 1) ? Wni : (mat == 2) ? Wnj : Wnode;
    float v = W[Lr * 16384 + c * 256 + r];
    __nv_bfloat16 h = __float2bfloat16(v);
    __nv_bfloat16 l = __float2bfloat16(v - __bfloat162float(h));
    unsigned sw = SWZ128((unsigned)(r * 128 + c * 2)) >> 1;
    g_wb[(size_t)((Lr * 4 + mat) * 2 + 0) * 16384 + sw] = h;
    g_wb[(size_t)((Lr * 4 + mat) * 2 + 1) * 16384 + sw] = l;
}

// ---------------- prep: W_mlp^T blobs ----------------
__global__ void k_prepw_mlp(const float* __restrict__ Wm) {
    int idx = blockIdx.x * 256 + threadIdx.x;   // 32768
    if (idx >= 32768) return;
    int Lr = idx >> 14;
    int rem = idx & 16383;
    int c = rem >> 12;
    int t = rem & 4095;
    int n = t >> 6, kk = t & 63;
    float v = Wm[Lr * 16384 + (c * 64 + kk) * 64 + n];
    __nv_bfloat16 h = __float2bfloat16(v);
    __nv_bfloat16 l = __float2bfloat16(v - __bfloat162float(h));
    unsigned sw = SWZ128((unsigned)(n * 128 + kk * 2)) >> 1;
    g_wmlp[(size_t)((Lr * 4 + c) * 2 + 0) * 4096 + sw] = h;
    g_wmlp[(size_t)((Lr * 4 + c) * 2 + 1) * 4096 + sw] = l;
}

// ---------------- shared HMMA core: one m16 sub of a 128x256 block ----------------
__device__ __forceinline__ void mma_sub_128x256(
    uint32_t sb32, uint32_t ahi, uint32_t alo, uint32_t bhi, uint32_t blo,
    int m0, int cg, int lane, float (&acc)[16][4]) {
    int a_lane_row = lane & 15;
    int a_lane_kb  = (lane >> 4) * 16;
    int b_lane_nr  = (lane & 7) + (lane >> 4) * 8;
    int b_lane_kb  = ((lane >> 3) & 1) * 16;
#pragma unroll
    for (int t = 0; t < 16; t++)
#pragma unroll
        for (int q = 0; q < 4; q++) acc[t][q] = 0.f;
#pragma unroll
    for (int pass = 0; pass < 3; pass++) {
        uint32_t Abase = sb32 + ((pass == 1) ? alo : ahi);
        uint32_t Bbase = sb32 + ((pass == 2) ? blo : bhi);
#pragma unroll
        for (int k0 = 0; k0 < 4; k0++) {
            uint32_t a0, a1, a2, a3;
            {
                unsigned off = (unsigned)((m0 + a_lane_row) * 128 + k0 * 32 + a_lane_kb);
                LDSM4(a0, a1, a2, a3, Abase + SWZ128(off));
            }
#pragma unroll
            for (int g = 0; g < 8; g++) {
                uint32_t b0, b1, b2, b3;
                int n0 = cg * 128 + g * 16;
                unsigned off = (unsigned)((n0 + b_lane_nr) * 128 + k0 * 32 + b_lane_kb);
                LDSM4(b0, b1, b2, b3, Bbase + SWZ128(off));
                MMA16816(acc[2 * g],     a0, a1, a2, a3, b0, b1);
                MMA16816(acc[2 * g + 1], a0, a1, a2, a3, b2, b3);
            }
        }
    }
}

// ---------------- HMMA node GEMM ----------------
#define SMN_AHI 0
#define SMN_ALO 16384
#define SMN_BHI 32768
#define SMN_BLO 65536
#define SMN_TOTAL 98304

__global__ __launch_bounds__(256, 2) void k_nodegemm_mma(int Lr) {
    extern __shared__ char smem[];
    uint32_t sb32 = smem_u32(smem);
    int tid = threadIdx.x;
    int wid = tid >> 5, lane = tid & 31;
    int row0 = blockIdx.x * 128;
    int nb = blockIdx.y;

    {
        const uint4* s1 = reinterpret_cast<const uint4*>(
            g_wb + (size_t)((Lr * 4 + nb + 1) * 2 + 0) * 16384);
        const uint4* s2 = reinterpret_cast<const uint4*>(
            g_wb + (size_t)((Lr * 4 + nb + 1) * 2 + 1) * 16384);
        uint4* d1 = reinterpret_cast<uint4*>(smem + SMN_BHI);
        uint4* d2 = reinterpret_cast<uint4*>(smem + SMN_BLO);
#pragma unroll
        for (int i = 0; i < 8; i++) {
            d1[tid + i * 256] = s1[tid + i * 256];
            d2[tid + i * 256] = s2[tid + i * 256];
        }
    }
    {
        int row = tid >> 1;
        int hc = (tid & 1) * 32;
        const float* ap = g_feat + (size_t)(row0 + row) * 64 + hc;
#pragma unroll
        for (int q = 0; q < 4; q++) {
            float4 va = *reinterpret_cast<const float4*>(ap + q * 8);
            float4 vb = *reinterpret_cast<const float4*>(ap + q * 8 + 4);
            uint4 H, L;
            split2(va.x, va.y, H.x, L.x);
            split2(va.z, va.w, H.y, L.y);
            split2(vb.x, vb.y, H.z, L.z);
            split2(vb.z, vb.w, H.w, L.w);
            unsigned sw = SWZ128((unsigned)(row * 128 + (hc + q * 8) * 2));
            *reinterpret_cast<uint4*>(smem + SMN_AHI + sw) = H;
            *reinterpret_cast<uint4*>(smem + SMN_ALO + sw) = L;
        }
    }
    __syncthreads();

    int rg = wid & 3;
    int cg = wid >> 2;
#pragma unroll
    for (int sub = 0; sub < 2; sub++) {
        int m0 = rg * 32 + sub * 16;
        float acc[16][4];
        mma_sub_128x256(sb32, SMN_AHI, SMN_ALO, SMN_BHI, SMN_BLO, m0, cg, lane, acc);

        int rquad = lane >> 2;
        int r_lo = row0 + m0 + rquad, r_hi = r_lo + 8;
        float* c_lo = g_cat + (size_t)r_lo * 768 + nb * 256;
        float* c_hi = g_cat + (size_t)r_hi * 768 + nb * 256;
#pragma unroll
        for (int tile = 0; tile < 16; tile++) {
            int n_ = cg * 128 + tile * 8 + (lane & 3) * 2;
            *reinterpret_cast<float2*>(c_lo + n_) = make_float2(acc[tile][0], acc[tile][1]);
            *reinterpret_cast<float2*>(c_hi + n_) = make_float2(acc[tile][2], acc[tile][3]);
        }
    }
}

// ---------------- HMMA fused edge logits (PERM order) ----------------
#define SM_SRC    0
#define SM_DST    512
#define SM_BATT   1024
#define SM_ATTN   2048
#define SM_AHI    4096
#define SM_ALO    20480
#define SM_BHI    36864
#define SM_BLO    69632
#define SM_EDGE_TOTAL 102400

__global__ __launch_bounds__(256, 2) void k_edge_mma(
    int Lr,
    const float* __restrict__ batt,
    const float* __restrict__ attn) {
    extern __shared__ char smem[];
    uint32_t sb32 = smem_u32(smem);
    int tid = threadIdx.x;
    int wid = tid >> 5, lane = tid & 31;
    int e0 = blockIdx.x * 128;

    ((float*)(smem + SM_BATT))[tid] = batt[tid];
    ((float*)(smem + SM_ATTN))[tid] = attn[tid];
    if (tid < 128) {
        ((int*)(smem + SM_SRC))[tid] = g_psrc[e0 + tid];
        ((int*)(smem + SM_DST))[tid] = g_pdst[e0 + tid];
    }

    {
        const uint4* s1 = reinterpret_cast<const uint4*>(
            g_wb + (size_t)((Lr * 4 + 0) * 2 + 0) * 16384);
        const uint4* s2 = reinterpret_cast<const uint4*>(
            g_wb + (size_t)((Lr * 4 + 0) * 2 + 1) * 16384);
        uint4* d1 = reinterpret_cast<uint4*>(smem + SM_BHI);
        uint4* d2 = reinterpret_cast<uint4*>(smem + SM_BLO);
#pragma unroll
        for (int i = 0; i < 8; i++) {
            d1[tid + i * 256] = s1[tid + i * 256];
            d2[tid + i * 256] = s2[tid + i * 256];
        }
    }
    {
        size_t byte_base = (size_t)blockIdx.x * 16384;
        const uint4* s1 = reinterpret_cast<const uint4*>(
            reinterpret_cast<const char*>(g_ehi) + byte_base);
        const uint4* s2 = reinterpret_cast<const uint4*>(
            reinterpret_cast<const char*>(g_elo) + byte_base);
        uint4* d1 = reinterpret_cast<uint4*>(smem + SM_AHI);
        uint4* d2 = reinterpret_cast<uint4*>(smem + SM_ALO);
#pragma unroll
        for (int i = 0; i < 4; i++) {
            d1[tid + i * 256] = s1[tid + i * 256];
            d2[tid + i * 256] = s2[tid + i * 256];
        }
    }
    __syncthreads();

    const int* ssrc = (const int*)(smem + SM_SRC);
    const int* sdst = (const int*)(smem + SM_DST);
    const float* sbp = (const float*)(smem + SM_BATT);
    const float* sap = (const float*)(smem + SM_ATTN);

    int rg = wid & 3;
    int cg = wid >> 2;

#pragma unroll
    for (int sub = 0; sub < 2; sub++) {
        int m0 = rg * 32 + sub * 16;
        float acc[16][4];
        mma_sub_128x256(sb32, SM_AHI, SM_ALO, SM_BHI, SM_BLO, m0, cg, lane, acc);

        int rquad = lane >> 2;
        int r_lo = m0 + rquad, r_hi = r_lo + 8;
        const float* ni_lo = g_cat + (size_t)ssrc[r_lo] * 768;
        const float* nj_lo = g_cat + (size_t)sdst[r_lo] * 768 + 256;
        const float* ni_hi = g_cat + (size_t)ssrc[r_hi] * 768;
        const float* nj_hi = g_cat + (size_t)sdst[r_hi] * 768 + 256;

        float pr00 = 0.f, pr01 = 0.f, pr10 = 0.f, pr11 = 0.f;
#pragma unroll
        for (int tile = 0; tile < 16; tile++) {
            int n_ = cg * 128 + tile * 8 + (lane & 3) * 2;
            float2 vb = *reinterpret_cast<const float2*>(&sbp[n_]);
            float2 va = *reinterpret_cast<const float2*>(&sap[n_]);
            float2 gli = *reinterpret_cast<const float2*>(&ni_lo[n_]);
            float2 glj = *reinterpret_cast<const float2*>(&nj_lo[n_]);
            float2 ghi = *reinterpret_cast<const float2*>(&ni_hi[n_]);
            float2 ghj = *reinterpret_cast<const float2*>(&nj_hi[n_]);
            float x0 = acc[tile][0] + gli.x + glj.x + vb.x;
            float x1 = acc[tile][1] + gli.y + glj.y + vb.y;
            float y0 = acc[tile][2] + ghi.x + ghj.x + vb.x;
            float y1 = acc[tile][3] + ghi.y + ghj.y + vb.y;
            x0 = (x0 > 0.f) ? x0 : 0.2f * x0;
            x1 = (x1 > 0.f) ? x1 : 0.2f * x1;
            y0 = (y0 > 0.f) ? y0 : 0.2f * y0;
            y1 = (y1 > 0.f) ? y1 : 0.2f * y1;
            float plo = x0 * va.x + x1 * va.y;
            float phi = y0 * va.x + y1 * va.y;
            if (tile < 8) { pr00 += plo; pr10 += phi; }
            else          { pr01 += plo; pr11 += phi; }
        }
#pragma unroll
        for (int o = 1; o <= 2; o <<= 1) {
            pr00 += __shfl_xor_sync(0xffffffffu, pr00, o);
            pr01 += __shfl_xor_sync(0xffffffffu, pr01, o);
            pr10 += __shfl_xor_sync(0xffffffffu, pr10, o);
            pr11 += __shfl_xor_sync(0xffffffffu, pr11, o);
        }
        if ((lane & 3) == 0) {
            *reinterpret_cast<float2*>(&g_elog[(size_t)(e0 + r_lo) * 4 + cg * 2]) =
                make_float2(pr00, pr01);
            *reinterpret_cast<float2*>(&g_elog[(size_t)(e0 + r_hi) * 4 + cg * 2]) =
                make_float2(pr10, pr11);
        }
    }
}

// ---------------- softmax + aggregation (linear CSR, unrolled gathers) ----------------
__global__ __launch_bounds__(256) void k_aggregate() {
    __shared__ float sw[8][32][4];
    __shared__ int   se[8][32];
    int tid = threadIdx.x;
    int w = tid >> 5, lane = tid & 31;
    int node = blockIdx.x * 8 + w;
    if (node >= NN) return;
    int lo = g_off[node], hi = g_off[node + 1];

    const float4* elog4 = reinterpret_cast<const float4*>(g_elog);

    float4 mx = make_float4(-1e30f, -1e30f, -1e30f, -1e30f);
    for (int i = lo + lane; i < hi; i += 32) {
        float4 v = elog4[i];
        mx.x = fmaxf(mx.x, v.x); mx.y = fmaxf(mx.y, v.y);
        mx.z = fmaxf(mx.z, v.z); mx.w = fmaxf(mx.w, v.w);
    }
#pragma unroll
    for (int o = 16; o; o >>= 1) {
        mx.x = fmaxf(mx.x, __shfl_xor_sync(0xffffffffu, mx.x, o));
        mx.y = fmaxf(mx.y, __shfl_xor_sync(0xffffffffu, mx.y, o));
        mx.z = fmaxf(mx.z, __shfl_xor_sync(0xffffffffu, mx.z, o));
        mx.w = fmaxf(mx.w, __shfl_xor_sync(0xffffffffu, mx.w, o));
    }

    float4 z = make_float4(0.f, 0.f, 0.f, 0.f);
    for (int i = lo + lane; i < hi; i += 32) {
        float4 v = elog4[i];
        z.x += __expf(v.x - mx.x); z.y += __expf(v.y - mx.y);
        z.z += __expf(v.z - mx.z); z.w += __expf(v.w - mx.w);
    }
#pragma unroll
    for (int o = 16; o; o >>= 1) {
        z.x += __shfl_xor_sync(0xffffffffu, z.x, o);
        z.y += __shfl_xor_sync(0xffffffffu, z.y, o);
        z.z += __shfl_xor_sync(0xffffffffu, z.z, o);
        z.w += __shfl_xor_sync(0xffffffffu, z.w, o);
    }
    float4 zi;
    zi.x = (z.x > 0.f) ? 1.f / z.x : 0.f;
    zi.y = (z.y > 0.f) ? 1.f / z.y : 0.f;
    zi.z = (z.z > 0.f) ? 1.f / z.z : 0.f;
    zi.w = (z.w > 0.f) ? 1.f / z.w : 0.f;

    // lane covers cols [lane*8, lane*8+8): head = lane>>3
    float4 a0 = make_float4(0.f, 0.f, 0.f, 0.f);
    float4 a1 = make_float4(0.f, 0.f, 0.f, 0.f);
    int hd = lane >> 3;

    for (int c0 = lo; c0 < hi; c0 += 32) {
        int i = c0 + lane;
        if (i < hi) {
            float4 v = elog4[i];
            sw[w][lane][0] = __expf(v.x - mx.x) * zi.x;
            sw[w][lane][1] = __expf(v.y - mx.y) * zi.y;
            sw[w][lane][2] = __expf(v.z - mx.z) * zi.z;
            sw[w][lane][3] = __expf(v.w - mx.w) * zi.w;
            se[w][lane] = g_psrc[i];
        }
        __syncwarp();
        int cnt = min(32, hi - c0);
        int u = 0;
        // unroll x2: issue both rows' loads before accumulating (2x MLP)
        for (; u + 2 <= cnt; u += 2) {
            float wg0 = sw[w][u][hd];
            float wg1 = sw[w][u + 1][hd];
            const float4* p0 = reinterpret_cast<const float4*>(
                g_cat + (size_t)se[w][u] * 768 + 512);
            const float4* p1 = reinterpret_cast<const float4*>(
                g_cat + (size_t)se[w][u + 1] * 768 + 512);
            float4 h00 = p0[lane * 2], h01 = p0[lane * 2 + 1];
            float4 h10 = p1[lane * 2], h11 = p1[lane * 2 + 1];
            a0.x += h00.x * wg0; a0.y += h00.y * wg0; a0.z += h00.z * wg0; a0.w += h00.w * wg0;
            a1.x += h01.x * wg0; a1.y += h01.y * wg0; a1.z += h01.z * wg0; a1.w += h01.w * wg0;
            a0.x += h10.x * wg1; a0.y += h10.y * wg1; a0.z += h10.z * wg1; a0.w += h10.w * wg1;
            a1.x += h11.x * wg1; a1.y += h11.y * wg1; a1.z += h11.z * wg1; a1.w += h11.w * wg1;
        }
        if (u < cnt) {
            float wgt = sw[w][u][hd];
            const float4* p0 = reinterpret_cast<const float4*>(
                g_cat + (size_t)se[w][u] * 768 + 512);
            float4 h0 = p0[lane * 2], h1 = p0[lane * 2 + 1];
            a0.x += h0.x * wgt; a0.y += h0.y * wgt; a0.z += h0.z * wgt; a0.w += h0.w * wgt;
            a1.x += h1.x * wgt; a1.y += h1.y * wgt; a1.z += h1.z * wgt; a1.w += h1.w * wgt;
        }
        __syncwarp();
    }
    float4* outp = reinterpret_cast<float4*>(g_agg + (size_t)node * 256 + lane * 8);
    outp[0] = a0;
    outp[1] = a1;
}

// ---------------- HMMA MLP + residual ----------------
#define SMM_AHI 0
#define SMM_ALO 16384
#define SMM_BHI 32768
#define SMM_BLO 40960
#define SMM_TOTAL 49152

__global__ __launch_bounds__(256) void k_mlp_mma(
    int Lr, const float* __restrict__ bm,
    float* __restrict__ out, int outbase) {
    extern __shared__ char smem[];
    uint32_t sb32 = smem_u32(smem);
    int tid = threadIdx.x;
    int wid = tid >> 5, lane = tid & 31;
    int row0 = blockIdx.x * 128;

    int a_lane_row = lane & 15;
    int a_lane_kb  = (lane >> 4) * 16;
    int b_lane_nr  = (lane & 7) + (lane >> 4) * 8;
    int b_lane_kb  = ((lane >> 3) & 1) * 16;
    int m0 = wid * 16;

    float acc[8][4];
#pragma unroll
    for (int t = 0; t < 8; t++)
#pragma unroll
        for (int q = 0; q < 4; q++) acc[t][q] = 0.f;

    for (int ch = 0; ch < 4; ch++) {
        __syncthreads();
        {
            const uint4* s1 = reinterpret_cast<const uint4*>(
                g_wmlp + (size_t)((Lr * 4 + ch) * 2 + 0) * 4096);
            const uint4* s2 = reinterpret_cast<const uint4*>(
                g_wmlp + (size_t)((Lr * 4 + ch) * 2 + 1) * 4096);
            uint4* d1 = reinterpret_cast<uint4*>(smem + SMM_BHI);
            uint4* d2 = reinterpret_cast<uint4*>(smem + SMM_BLO);
#pragma unroll
            for (int i = 0; i < 2; i++) {
                d1[tid + i * 256] = s1[tid + i * 256];
                d2[tid + i * 256] = s2[tid + i * 256];
            }
        }
        {
            int row = tid >> 1;
            int hc = (tid & 1) * 32;
            const float* ap = g_agg + (size_t)(row0 + row) * 256 + ch * 64 + hc;
#pragma unroll
            for (int q = 0; q < 4; q++) {
                float4 va = *reinterpret_cast<const float4*>(ap + q * 8);
                float4 vb = *reinterpret_cast<const float4*>(ap + q * 8 + 4);
                uint4 H, L;
                split2(va.x, va.y, H.x, L.x);
                split2(va.z, va.w, H.y, L.y);
                split2(vb.x, vb.y, H.z, L.z);
                split2(vb.z, vb.w, H.w, L.w);
                unsigned sw = SWZ128((unsigned)(row * 128 + (hc + q * 8) * 2));
                *reinterpret_cast<uint4*>(smem + SMM_AHI + sw) = H;
                *reinterpret_cast<uint4*>(smem + SMM_ALO + sw) = L;
            }
        }
        __syncthreads();

#pragma unroll
        for (int pass = 0; pass < 3; pass++) {
            uint32_t Abase = sb32 + ((pass == 1) ? SMM_ALO : SMM_AHI);
            uint32_t Bbase = sb32 + ((pass == 2) ? SMM_BLO : SMM_BHI);
#pragma unroll
            for (int k0 = 0; k0 < 4; k0++) {
                uint32_t a0, a1, a2, a3;
                {
                    unsigned off = (unsigned)((m0 + a_lane_row) * 128 + k0 * 32 + a_lane_kb);
                    LDSM4(a0, a1, a2, a3, Abase + SWZ128(off));
                }
#pragma unroll
                for (int g = 0; g < 4; g++) {
                    uint32_t b0, b1, b2, b3;
                    int n0 = g * 16;
                    unsigned off = (unsigned)((n0 + b_lane_nr) * 128 + k0 * 32 + b_lane_kb);
                    LDSM4(b0, b1, b2, b3, Bbase + SWZ128(off));
                    MMA16816(acc[2 * g],     a0, a1, a2, a3, b0, b1);
                    MMA16816(acc[2 * g + 1], a0, a1, a2, a3, b2, b3);
                }
            }
        }
    }

    int rquad = lane >> 2;
    int r_lo = row0 + m0 + rquad, r_hi = r_lo + 8;
#pragma unroll
    for (int tile = 0; tile < 8; tile++) {
        int n_ = tile * 8 + (lane & 3) * 2;
        float2 vb = *reinterpret_cast<const float2*>(&bm[n_]);
        if (r_lo < NN) {
            float2 f = *reinterpret_cast<const float2*>(&g_feat[(size_t)r_lo * 64 + n_]);
            float v0 = acc[tile][0] + vb.x + f.x;
            float v1 = acc[tile][1] + vb.y + f.y;
            *reinterpret_cast<float2*>(&g_feat[(size_t)r_lo * 64 + n_]) = make_float2(v0, v1);
            *reinterpret_cast<float2*>(&out[(size_t)r_lo * OUTW + outbase + n_]) =
                make_float2(v0, v1);
        }
        if (r_hi < NN) {
            float2 f = *reinterpret_cast<const float2*>(&g_feat[(size_t)r_hi * 64 + n_]);
            float v0 = acc[tile][2] + vb.x + f.x;
            float v1 = acc[tile][3] + vb.y + f.y;
            *reinterpret_cast<float2*>(&g_feat[(size_t)r_hi * 64 + n_]) = make_float2(v0, v1);
            *reinterpret_cast<float2*>(&out[(size_t)r_hi * OUTW + outbase + n_]) =
                make_float2(v0, v1);
        }
    }
}

// ---------------- launch ----------------
extern "C" void kernel_launch(void* const* d_in, const int* in_sizes, int n_in,
                              void* d_out, int out_size) {
    const float* node_feat = (const float*)d_in[0];
    const float* edge_feat = (const float*)d_in[1];
    const int*   src       = (const int*)d_in[2];
    const int*   dst       = (const int*)d_in[3];
    const float* W_embed   = (const float*)d_in[4];
    const float* b_embed   = (const float*)d_in[5];
    const float* W_ni      = (const float*)d_in[6];
    const float* W_nj      = (const float*)d_in[7];
    const float* W_fij     = (const float*)d_in[8];
    const float* b_att     = (const float*)d_in[9];
    const float* attn      = (const float*)d_in[10];
    const float* W_node    = (const float*)d_in[11];
    const float* W_mlp     = (const float*)d_in[12];
    const float* b_mlp     = (const float*)d_in[13];
    float* out = (float*)d_out;

    cudaFuncSetAttribute(k_edge_mma, cudaFuncAttributeMaxDynamicSharedMemorySize,
                         SM_EDGE_TOTAL);
    cudaFuncSetAttribute(k_nodegemm_mma, cudaFuncAttributeMaxDynamicSharedMemorySize,
                         SMN_TOTAL);
    cudaFuncSetAttribute(k_mlp_mma, cudaFuncAttributeMaxDynamicSharedMemorySize,
                         SMM_TOTAL);

    // CSR by dst (+ perm-order src/dst); scan also seeds cursor
    k_zero_cursor<<<(NN + 255) / 256, 256>>>();
    k_degree<<<(EE + 255) / 256, 256>>>(dst);
    k_scan<<<1, 1024>>>();
    k_scatter<<<(EE + 255) / 256, 256>>>(src, dst);

    // preps
    k_prep_edge<<<(EE * 8 + 255) / 256, 256>>>(edge_feat);
    k_prepw<<<512, 256>>>(W_fij, W_ni, W_nj, W_node);
    k_prepw_mlp<<<128, 256>>>(W_mlp);

    // embed (+ raw feature copy)
    k_embed<<<NN / 4, 256>>>(node_feat, W_embed, b_embed, out);

    for (int L = 0; L < 2; L++) {
        const float* ba = b_att + L * 256;
        const float* at = attn  + L * 256;
        const float* bm = b_mlp + L * 64;

        dim3 ng(NPAD / 128, 3);
        k_nodegemm_mma<<<ng, 256, SMN_TOTAL>>>(L);
        k_edge_mma<<<EE / 128, 256, SM_EDGE_TOTAL>>>(L, ba, at);
        k_aggregate<<<NN / 8, 256>>>();
        k_mlp_mma<<<NPAD / 128, 256, SMM_TOTAL>>>(L, bm, out, 80 + 64 * L);
    }
}

// round 16
// speedup vs baseline: 1.4919x; 1.4919x over previous
#include <cuda_runtime.h>
#include <cuda_bf16.h>
#include <cstdint>

// Problem constants
#define NN    20000
#define EE    320000
#define NPAD  20096        // 157 * 128
#define OUTW  208          // 16 + 3*64

#define SWZ128(b) ((b) ^ (((b) >> 3) & 0x70))

// ---- warp-level tensor core primitives (arch-generic PTX, compiles for sm_103) ----
#define LDSM4(r0, r1, r2, r3, addr) \
    asm volatile("ldmatrix.sync.aligned.m8n8.x4.shared.b16 {%0,%1,%2,%3}, [%4];" \
        : "=r"(r0), "=r"(r1), "=r"(r2), "=r"(r3) : "r"(addr))

#define MMA16816(d, a0, a1, a2, a3, b0, b1) \
    asm volatile("mma.sync.aligned.m16n8k16.row.col.f32.bf16.bf16.f32 " \
        "{%0,%1,%2,%3}, {%4,%5,%6,%7}, {%8,%9}, {%0,%1,%2,%3};" \
        : "+f"((d)[0]), "+f"((d)[1]), "+f"((d)[2]), "+f"((d)[3]) \
        : "r"(a0), "r"(a1), "r"(a2), "r"(a3), "r"(b0), "r"(b1))

__device__ __forceinline__ uint32_t smem_u32(const void* p) {
    uint32_t a;
    asm("{ .reg .u64 t; cvta.to.shared.u64 t, %1; cvt.u32.u64 %0, t; }"
        : "=r"(a) : "l"(p));
    return a;
}

// packed bf16x2 convert: lo half = x, hi half = y
__device__ __forceinline__ uint32_t cvt_bf2(float x, float y) {
    uint32_t r;
    asm("cvt.rn.bf16x2.f32 %0, %1, %2;" : "=r"(r) : "f"(y), "f"(x));
    return r;
}
__device__ __forceinline__ void split2(float x, float y, uint32_t& h, uint32_t& l) {
    h = cvt_bf2(x, y);
    float hx = __uint_as_float(h << 16);
    float hy = __uint_as_float(h & 0xffff0000u);
    l = cvt_bf2(x - hx, y - hy);
}

// ---------------- scratch (device globals; no allocation) ----------------
__device__ float g_feat[NPAD * 64];
__device__ float g_cat[NPAD * 768];          // [f_ni | f_nj | hn]
__device__ float g_elog[EE * 4];             // PERM order
__device__ float g_agg[NPAD * 256];
__device__ int   g_off[NN + 1];
__device__ int   g_cursor[NN];
__device__ int   g_perm[EE];
__device__ int   g_psrc[EE];
__device__ int   g_pdst[EE];
__device__ __nv_bfloat16 g_ehi[EE * 64];
__device__ __nv_bfloat16 g_elo[EE * 64];
// W^T blobs: [layer][mat: fij,ni,nj,node][hi/lo] each 256x64 swizzled
__device__ __nv_bfloat16 g_wb[2 * 4 * 2 * 16384];
// W_mlp^T blobs: [layer][kchunk 0..3][hi/lo] each 64 rows x 64 K swizzled
__device__ __nv_bfloat16 g_wmlp[2 * 4 * 2 * 4096];

// ---------------- CSR build ----------------
__global__ void k_zero_cursor() {
    int i = blockIdx.x * blockDim.x + threadIdx.x;
    if (i < NN) g_cursor[i] = 0;
}
__global__ void k_degree(const int* __restrict__ dst) {
    int e = blockIdx.x * blockDim.x + threadIdx.x;
    if (e < EE) atomicAdd(&g_cursor[dst[e]], 1);
}
// scan writes g_off (inclusive, shifted) AND g_cursor (exclusive prefix)
__global__ void k_scan() {
    __shared__ int s[1024];
    __shared__ int carry;
    int t = threadIdx.x;
    if (t == 0) { carry = 0; g_off[0] = 0; }
    __syncthreads();
    for (int base = 0; base < NN; base += 1024) {
        int x = (base + t < NN) ? g_cursor[base + t] : 0;
        s[t] = x;
        __syncthreads();
        for (int d = 1; d < 1024; d <<= 1) {
            int v = (t >= d) ? s[t - d] : 0;
            __syncthreads();
            s[t] += v;
            __syncthreads();
        }
        if (base + t < NN) {
            int inc = carry + s[t];
            g_off[base + t + 1] = inc;
            g_cursor[base + t] = inc - x;   // exclusive prefix for scatter
        }
        __syncthreads();
        if (t == 0) carry += s[1023];
        __syncthreads();
    }
}
__global__ void k_scatter(const int* __restrict__ src, const int* __restrict__ dst) {
    int e = blockIdx.x * blockDim.x + threadIdx.x;
    if (e < EE) {
        int d = dst[e];
        int p = atomicAdd(&g_cursor[d], 1);
        g_perm[p] = e;
        g_psrc[p] = src[e];
        g_pdst[p] = d;
    }
}

// ---------------- embed (+ raw feature copy, cols 0..15) ----------------
__global__ void k_embed(const float* __restrict__ nf,
                        const float* __restrict__ W, const float* __restrict__ b,
                        float* __restrict__ out) {
    __shared__ float sW[16 * 64];
    int tid = threadIdx.x;
#pragma unroll
    for (int i = 0; i < 4; i++) sW[tid + i * 256] = W[tid + i * 256];
    __syncthreads();
    int n = blockIdx.x * 4 + (tid >> 6);
    int c = tid & 63;
    if (n < NN) {
        float acc = b[c];
        const float* r = nf + n * 16;
#pragma unroll
        for (int k = 0; k < 16; k++) acc += r[k] * sW[k * 64 + c];
        g_feat[n * 64 + c] = acc;
        out[n * OUTW + 16 + c] = acc;
        if (c < 16) out[n * OUTW + c] = r[c];   // raw node features
    }
}

// ---------------- prep: edge_feat bf16 split, pre-swizzled, PERM order ----------------
__global__ void k_prep_edge(const float* __restrict__ ef) {
    int idx = blockIdx.x * 256 + threadIdx.x;
    if (idx >= EE * 8) return;
    int p = idx >> 3, q = idx & 7;
    int e = g_perm[p];
    const float* ep = ef + (size_t)e * 64 + q * 8;
    float4 a = *reinterpret_cast<const float4*>(ep);
    float4 b = *reinterpret_cast<const float4*>(ep + 4);
    uint4 H, L;
    split2(a.x, a.y, H.x, L.x);
    split2(a.z, a.w, H.y, L.y);
    split2(b.x, b.y, H.z, L.z);
    split2(b.z, b.w, H.w, L.w);
    unsigned sw = SWZ128((unsigned)((p & 127) * 128 + q * 16));
    size_t byte_base = (size_t)(p >> 7) * 16384;
    *reinterpret_cast<uint4*>(reinterpret_cast<char*>(g_ehi) + byte_base + sw) = H;
    *reinterpret_cast<uint4*>(reinterpret_cast<char*>(g_elo) + byte_base + sw) = L;
}

// ---------------- prep: W^T blobs (fij, ni, nj, node) ----------------
__global__ void k_prepw(const float* __restrict__ Wfij, const float* __restrict__ Wni,
                        const float* __restrict__ Wnj, const float* __restrict__ Wnode) {
    int idx = blockIdx.x * 256 + threadIdx.x;   // 131072
    if (idx >= 131072) return;
    int Lr = idx >> 16;
    int rem = idx & 65535;
    int mat = rem >> 14;
    int t = rem & 16383;
    int r = t >> 6, c = t & 63;
    const float* W = (mat == 0) ? Wfij : (mat == 1) ? Wni : (mat == 2) ? Wnj : Wnode;
    float v = W[Lr * 16384 + c * 256 + r];
    __nv_bfloat16 h = __float2bfloat16(v);
    __nv_bfloat16 l = __float2bfloat16(v - __bfloat162float(h));
    unsigned sw = SWZ128((unsigned)(r * 128 + c * 2)) >> 1;
    g_wb[(size_t)((Lr * 4 + mat) * 2 + 0) * 16384 + sw] = h;
    g_wb[(size_t)((Lr * 4 + mat) * 2 + 1) * 16384 + sw] = l;
}

// ---------------- prep: W_mlp^T blobs ----------------
__global__ void k_prepw_mlp(const float* __restrict__ Wm) {
    int idx = blockIdx.x * 256 + threadIdx.x;   // 32768
    if (idx >= 32768) return;
    int Lr = idx >> 14;
    int rem = idx & 16383;
    int c = rem >> 12;
    int t = rem & 4095;
    int n = t >> 6, kk = t & 63;
    float v = Wm[Lr * 16384 + (c * 64 + kk) * 64 + n];
    __nv_bfloat16 h = __float2bfloat16(v);
    __nv_bfloat16 l = __float2bfloat16(v - __bfloat162float(h));
    unsigned sw = SWZ128((unsigned)(n * 128 + kk * 2)) >> 1;
    g_wmlp[(size_t)((Lr * 4 + c) * 2 + 0) * 4096 + sw] = h;
    g_wmlp[(size_t)((Lr * 4 + c) * 2 + 1) * 4096 + sw] = l;
}

// ---------------- shared HMMA core: one m16 sub of a 128x256 block ----------------
__device__ __forceinline__ void mma_sub_128x256(
    uint32_t sb32, uint32_t ahi, uint32_t alo, uint32_t bhi, uint32_t blo,
    int m0, int cg, int lane, float (&acc)[16][4]) {
    int a_lane_row = lane & 15;
    int a_lane_kb  = (lane >> 4) * 16;
    int b_lane_nr  = (lane & 7) + (lane >> 4) * 8;
    int b_lane_kb  = ((lane >> 3) & 1) * 16;
#pragma unroll
    for (int t = 0; t < 16; t++)
#pragma unroll
        for (int q = 0; q < 4; q++) acc[t][q] = 0.f;
#pragma unroll
    for (int pass = 0; pass < 3; pass++) {
        uint32_t Abase = sb32 + ((pass == 1) ? alo : ahi);
        uint32_t Bbase = sb32 + ((pass == 2) ? blo : bhi);
#pragma unroll
        for (int k0 = 0; k0 < 4; k0++) {
            uint32_t a0, a1, a2, a3;
            {
                unsigned off = (unsigned)((m0 + a_lane_row) * 128 + k0 * 32 + a_lane_kb);
                LDSM4(a0, a1, a2, a3, Abase + SWZ128(off));
            }
#pragma unroll
            for (int g = 0; g < 8; g++) {
                uint32_t b0, b1, b2, b3;
                int n0 = cg * 128 + g * 16;
                unsigned off = (unsigned)((n0 + b_lane_nr) * 128 + k0 * 32 + b_lane_kb);
                LDSM4(b0, b1, b2, b3, Bbase + SWZ128(off));
                MMA16816(acc[2 * g],     a0, a1, a2, a3, b0, b1);
                MMA16816(acc[2 * g + 1], a0, a1, a2, a3, b2, b3);
            }
        }
    }
}

// ---------------- HMMA node GEMM ----------------
#define SMN_AHI 0
#define SMN_ALO 16384
#define SMN_BHI 32768
#define SMN_BLO 65536
#define SMN_TOTAL 98304

__global__ __launch_bounds__(256) void k_nodegemm_mma(int Lr) {
    extern __shared__ char smem[];
    uint32_t sb32 = smem_u32(smem);
    int tid = threadIdx.x;
    int wid = tid >> 5, lane = tid & 31;
    int row0 = blockIdx.x * 128;
    int nb = blockIdx.y;

    {
        const uint4* s1 = reinterpret_cast<const uint4*>(
            g_wb + (size_t)((Lr * 4 + nb + 1) * 2 + 0) * 16384);
        const uint4* s2 = reinterpret_cast<const uint4*>(
            g_wb + (size_t)((Lr * 4 + nb + 1) * 2 + 1) * 16384);
        uint4* d1 = reinterpret_cast<uint4*>(smem + SMN_BHI);
        uint4* d2 = reinterpret_cast<uint4*>(smem + SMN_BLO);
#pragma unroll
        for (int i = 0; i < 8; i++) {
            d1[tid + i * 256] = s1[tid + i * 256];
            d2[tid + i * 256] = s2[tid + i * 256];
        }
    }
    {
        int row = tid >> 1;
        int hc = (tid & 1) * 32;
        const float* ap = g_feat + (size_t)(row0 + row) * 64 + hc;
#pragma unroll
        for (int q = 0; q < 4; q++) {
            float4 va = *reinterpret_cast<const float4*>(ap + q * 8);
            float4 vb = *reinterpret_cast<const float4*>(ap + q * 8 + 4);
            uint4 H, L;
            split2(va.x, va.y, H.x, L.x);
            split2(va.z, va.w, H.y, L.y);
            split2(vb.x, vb.y, H.z, L.z);
            split2(vb.z, vb.w, H.w, L.w);
            unsigned sw = SWZ128((unsigned)(row * 128 + (hc + q * 8) * 2));
            *reinterpret_cast<uint4*>(smem + SMN_AHI + sw) = H;
            *reinterpret_cast<uint4*>(smem + SMN_ALO + sw) = L;
        }
    }
    __syncthreads();

    int rg = wid & 3;
    int cg = wid >> 2;
#pragma unroll
    for (int sub = 0; sub < 2; sub++) {
        int m0 = rg * 32 + sub * 16;
        float acc[16][4];
        mma_sub_128x256(sb32, SMN_AHI, SMN_ALO, SMN_BHI, SMN_BLO, m0, cg, lane, acc);

        int rquad = lane >> 2;
        int r_lo = row0 + m0 + rquad, r_hi = r_lo + 8;
        float* c_lo = g_cat + (size_t)r_lo * 768 + nb * 256;
        float* c_hi = g_cat + (size_t)r_hi * 768 + nb * 256;
#pragma unroll
        for (int tile = 0; tile < 16; tile++) {
            int n_ = cg * 128 + tile * 8 + (lane & 3) * 2;
            *reinterpret_cast<float2*>(c_lo + n_) = make_float2(acc[tile][0], acc[tile][1]);
            *reinterpret_cast<float2*>(c_hi + n_) = make_float2(acc[tile][2], acc[tile][3]);
        }
    }
}

// ---------------- HMMA fused edge logits (PERM order) ----------------
#define SM_SRC    0
#define SM_DST    512
#define SM_BATT   1024
#define SM_ATTN   2048
#define SM_AHI    4096
#define SM_ALO    20480
#define SM_BHI    36864
#define SM_BLO    69632
#define SM_EDGE_TOTAL 102400

__global__ __launch_bounds__(256) void k_edge_mma(
    int Lr,
    const float* __restrict__ batt,
    const float* __restrict__ attn) {
    extern __shared__ char smem[];
    uint32_t sb32 = smem_u32(smem);
    int tid = threadIdx.x;
    int wid = tid >> 5, lane = tid & 31;
    int e0 = blockIdx.x * 128;

    ((float*)(smem + SM_BATT))[tid] = batt[tid];
    ((float*)(smem + SM_ATTN))[tid] = attn[tid];
    if (tid < 128) {
        ((int*)(smem + SM_SRC))[tid] = g_psrc[e0 + tid];
        ((int*)(smem + SM_DST))[tid] = g_pdst[e0 + tid];
    }

    {
        const uint4* s1 = reinterpret_cast<const uint4*>(
            g_wb + (size_t)((Lr * 4 + 0) * 2 + 0) * 16384);
        const uint4* s2 = reinterpret_cast<const uint4*>(
            g_wb + (size_t)((Lr * 4 + 0) * 2 + 1) * 16384);
        uint4* d1 = reinterpret_cast<uint4*>(smem + SM_BHI);
        uint4* d2 = reinterpret_cast<uint4*>(smem + SM_BLO);
#pragma unroll
        for (int i = 0; i < 8; i++) {
            d1[tid + i * 256] = s1[tid + i * 256];
            d2[tid + i * 256] = s2[tid + i * 256];
        }
    }
    {
        size_t byte_base = (size_t)blockIdx.x * 16384;
        const uint4* s1 = reinterpret_cast<const uint4*>(
            reinterpret_cast<const char*>(g_ehi) + byte_base);
        const uint4* s2 = reinterpret_cast<const uint4*>(
            reinterpret_cast<const char*>(g_elo) + byte_base);
        uint4* d1 = reinterpret_cast<uint4*>(smem + SM_AHI);
        uint4* d2 = reinterpret_cast<uint4*>(smem + SM_ALO);
#pragma unroll
        for (int i = 0; i < 4; i++) {
            d1[tid + i * 256] = s1[tid + i * 256];
            d2[tid + i * 256] = s2[tid + i * 256];
        }
    }
    __syncthreads();

    const int* ssrc = (const int*)(smem + SM_SRC);
    const int* sdst = (const int*)(smem + SM_DST);
    const float* sbp = (const float*)(smem + SM_BATT);
    const float* sap = (const float*)(smem + SM_ATTN);

    int rg = wid & 3;
    int cg = wid >> 2;

#pragma unroll
    for (int sub = 0; sub < 2; sub++) {
        int m0 = rg * 32 + sub * 16;
        float acc[16][4];
        mma_sub_128x256(sb32, SM_AHI, SM_ALO, SM_BHI, SM_BLO, m0, cg, lane, acc);

        int rquad = lane >> 2;
        int r_lo = m0 + rquad, r_hi = r_lo + 8;
        const float* ni_lo = g_cat + (size_t)ssrc[r_lo] * 768;
        const float* nj_lo = g_cat + (size_t)sdst[r_lo] * 768 + 256;
        const float* ni_hi = g_cat + (size_t)ssrc[r_hi] * 768;
        const float* nj_hi = g_cat + (size_t)sdst[r_hi] * 768 + 256;

        float pr00 = 0.f, pr01 = 0.f, pr10 = 0.f, pr11 = 0.f;
#pragma unroll
        for (int tile = 0; tile < 16; tile++) {
            int n_ = cg * 128 + tile * 8 + (lane & 3) * 2;
            float2 vb = *reinterpret_cast<const float2*>(&sbp[n_]);
            float2 va = *reinterpret_cast<const float2*>(&sap[n_]);
            float2 gli = *reinterpret_cast<const float2*>(&ni_lo[n_]);
            float2 glj = *reinterpret_cast<const float2*>(&nj_lo[n_]);
            float2 ghi = *reinterpret_cast<const float2*>(&ni_hi[n_]);
            float2 ghj = *reinterpret_cast<const float2*>(&nj_hi[n_]);
            float x0 = acc[tile][0] + gli.x + glj.x + vb.x;
            float x1 = acc[tile][1] + gli.y + glj.y + vb.y;
            float y0 = acc[tile][2] + ghi.x + ghj.x + vb.x;
            float y1 = acc[tile][3] + ghi.y + ghj.y + vb.y;
            x0 = (x0 > 0.f) ? x0 : 0.2f * x0;
            x1 = (x1 > 0.f) ? x1 : 0.2f * x1;
            y0 = (y0 > 0.f) ? y0 : 0.2f * y0;
            y1 = (y1 > 0.f) ? y1 : 0.2f * y1;
            float plo = x0 * va.x + x1 * va.y;
            float phi = y0 * va.x + y1 * va.y;
            if (tile < 8) { pr00 += plo; pr10 += phi; }
            else          { pr01 += plo; pr11 += phi; }
        }
#pragma unroll
        for (int o = 1; o <= 2; o <<= 1) {
            pr00 += __shfl_xor_sync(0xffffffffu, pr00, o);
            pr01 += __shfl_xor_sync(0xffffffffu, pr01, o);
            pr10 += __shfl_xor_sync(0xffffffffu, pr10, o);
            pr11 += __shfl_xor_sync(0xffffffffu, pr11, o);
        }
        if ((lane & 3) == 0) {
            *reinterpret_cast<float2*>(&g_elog[(size_t)(e0 + r_lo) * 4 + cg * 2]) =
                make_float2(pr00, pr01);
            *reinterpret_cast<float2*>(&g_elog[(size_t)(e0 + r_hi) * 4 + cg * 2]) =
                make_float2(pr10, pr11);
        }
    }
}

// ---------------- softmax + aggregation (linear CSR, unrolled gathers) ----------------
__global__ __launch_bounds__(256) void k_aggregate() {
    __shared__ float sw[8][32][4];
    __shared__ int   se[8][32];
    int tid = threadIdx.x;
    int w = tid >> 5, lane = tid & 31;
    int node = blockIdx.x * 8 + w;
    if (node >= NN) return;
    int lo = g_off[node], hi = g_off[node + 1];

    const float4* elog4 = reinterpret_cast<const float4*>(g_elog);

    float4 mx = make_float4(-1e30f, -1e30f, -1e30f, -1e30f);
    for (int i = lo + lane; i < hi; i += 32) {
        float4 v = elog4[i];
        mx.x = fmaxf(mx.x, v.x); mx.y = fmaxf(mx.y, v.y);
        mx.z = fmaxf(mx.z, v.z); mx.w = fmaxf(mx.w, v.w);
    }
#pragma unroll
    for (int o = 16; o; o >>= 1) {
        mx.x = fmaxf(mx.x, __shfl_xor_sync(0xffffffffu, mx.x, o));
        mx.y = fmaxf(mx.y, __shfl_xor_sync(0xffffffffu, mx.y, o));
        mx.z = fmaxf(mx.z, __shfl_xor_sync(0xffffffffu, mx.z, o));
        mx.w = fmaxf(mx.w, __shfl_xor_sync(0xffffffffu, mx.w, o));
    }

    float4 z = make_float4(0.f, 0.f, 0.f, 0.f);
    for (int i = lo + lane; i < hi; i += 32) {
        float4 v = elog4[i];
        z.x += __expf(v.x - mx.x); z.y += __expf(v.y - mx.y);
        z.z += __expf(v.z - mx.z); z.w += __expf(v.w - mx.w);
    }
#pragma unroll
    for (int o = 16; o; o >>= 1) {
        z.x += __shfl_xor_sync(0xffffffffu, z.x, o);
        z.y += __shfl_xor_sync(0xffffffffu, z.y, o);
        z.z += __shfl_xor_sync(0xffffffffu, z.z, o);
        z.w += __shfl_xor_sync(0xffffffffu, z.w, o);
    }
    float4 zi;
    zi.x = (z.x > 0.f) ? 1.f / z.x : 0.f;
    zi.y = (z.y > 0.f) ? 1.f / z.y : 0.f;
    zi.z = (z.z > 0.f) ? 1.f / z.z : 0.f;
    zi.w = (z.w > 0.f) ? 1.f / z.w : 0.f;

    // lane covers cols [lane*8, lane*8+8): head = lane>>3
    float4 a0 = make_float4(0.f, 0.f, 0.f, 0.f);
    float4 a1 = make_float4(0.f, 0.f, 0.f, 0.f);
    int hd = lane >> 3;

    for (int c0 = lo; c0 < hi; c0 += 32) {
        int i = c0 + lane;
        if (i < hi) {
            float4 v = elog4[i];
            sw[w][lane][0] = __expf(v.x - mx.x) * zi.x;
            sw[w][lane][1] = __expf(v.y - mx.y) * zi.y;
            sw[w][lane][2] = __expf(v.z - mx.z) * zi.z;
            sw[w][lane][3] = __expf(v.w - mx.w) * zi.w;
            se[w][lane] = g_psrc[i];
        }
        __syncwarp();
        int cnt = min(32, hi - c0);
        int u = 0;
        for (; u + 2 <= cnt; u += 2) {
            float wg0 = sw[w][u][hd];
            float wg1 = sw[w][u + 1][hd];
            const float4* p0 = reinterpret_cast<const float4*>(
                g_cat + (size_t)se[w][u] * 768 + 512);
            const float4* p1 = reinterpret_cast<const float4*>(
                g_cat + (size_t)se[w][u + 1] * 768 + 512);
            float4 h00 = p0[lane * 2], h01 = p0[lane * 2 + 1];
            float4 h10 = p1[lane * 2], h11 = p1[lane * 2 + 1];
            a0.x += h00.x * wg0; a0.y += h00.y * wg0; a0.z += h00.z * wg0; a0.w += h00.w * wg0;
            a1.x += h01.x * wg0; a1.y += h01.y * wg0; a1.z += h01.z * wg0; a1.w += h01.w * wg0;
            a0.x += h10.x * wg1; a0.y += h10.y * wg1; a0.z += h10.z * wg1; a0.w += h10.w * wg1;
            a1.x += h11.x * wg1; a1.y += h11.y * wg1; a1.z += h11.z * wg1; a1.w += h11.w * wg1;
        }
        if (u < cnt) {
            float wgt = sw[w][u][hd];
            const float4* p0 = reinterpret_cast<const float4*>(
                g_cat + (size_t)se[w][u] * 768 + 512);
            float4 h0 = p0[lane * 2], h1 = p0[lane * 2 + 1];
            a0.x += h0.x * wgt; a0.y += h0.y * wgt; a0.z += h0.z * wgt; a0.w += h0.w * wgt;
            a1.x += h1.x * wgt; a1.y += h1.y * wgt; a1.z += h1.z * wgt; a1.w += h1.w * wgt;
        }
        __syncwarp();
    }
    float4* outp = reinterpret_cast<float4*>(g_agg + (size_t)node * 256 + lane * 8);
    outp[0] = a0;
    outp[1] = a1;
}

// ---------------- HMMA MLP + residual ----------------
#define SMM_AHI 0
#define SMM_ALO 16384
#define SMM_BHI 32768
#define SMM_BLO 40960
#define SMM_TOTAL 49152

__global__ __launch_bounds__(256) void k_mlp_mma(
    int Lr, const float* __restrict__ bm,
    float* __restrict__ out, int outbase) {
    extern __shared__ char smem[];
    uint32_t sb32 = smem_u32(smem);
    int tid = threadIdx.x;
    int wid = tid >> 5, lane = tid & 31;
    int row0 = blockIdx.x * 128;

    int a_lane_row = lane & 15;
    int a_lane_kb  = (lane >> 4) * 16;
    int b_lane_nr  = (lane & 7) + (lane >> 4) * 8;
    int b_lane_kb  = ((lane >> 3) & 1) * 16;
    int m0 = wid * 16;

    float acc[8][4];
#pragma unroll
    for (int t = 0; t < 8; t++)
#pragma unroll
        for (int q = 0; q < 4; q++) acc[t][q] = 0.f;

    for (int ch = 0; ch < 4; ch++) {
        __syncthreads();
        {
            const uint4* s1 = reinterpret_cast<const uint4*>(
                g_wmlp + (size_t)((Lr * 4 + ch) * 2 + 0) * 4096);
            const uint4* s2 = reinterpret_cast<const uint4*>(
                g_wmlp + (size_t)((Lr * 4 + ch) * 2 + 1) * 4096);
            uint4* d1 = reinterpret_cast<uint4*>(smem + SMM_BHI);
            uint4* d2 = reinterpret_cast<uint4*>(smem + SMM_BLO);
#pragma unroll
            for (int i = 0; i < 2; i++) {
                d1[tid + i * 256] = s1[tid + i * 256];
                d2[tid + i * 256] = s2[tid + i * 256];
            }
        }
        {
            int row = tid >> 1;
            int hc = (tid & 1) * 32;
            const float* ap = g_agg + (size_t)(row0 + row) * 256 + ch * 64 + hc;
#pragma unroll
            for (int q = 0; q < 4; q++) {
                float4 va = *reinterpret_cast<const float4*>(ap + q * 8);
                float4 vb = *reinterpret_cast<const float4*>(ap + q * 8 + 4);
                uint4 H, L;
                split2(va.x, va.y, H.x, L.x);
                split2(va.z, va.w, H.y, L.y);
                split2(vb.x, vb.y, H.z, L.z);
                split2(vb.z, vb.w, H.w, L.w);
                unsigned sw = SWZ128((unsigned)(row * 128 + (hc + q * 8) * 2));
                *reinterpret_cast<uint4*>(smem + SMM_AHI + sw) = H;
                *reinterpret_cast<uint4*>(smem + SMM_ALO + sw) = L;
            }
        }
        __syncthreads();

#pragma unroll
        for (int pass = 0; pass < 3; pass++) {
            uint32_t Abase = sb32 + ((pass == 1) ? SMM_ALO : SMM_AHI);
            uint32_t Bbase = sb32 + ((pass == 2) ? SMM_BLO : SMM_BHI);
#pragma unroll
            for (int k0 = 0; k0 < 4; k0++) {
                uint32_t a0, a1, a2, a3;
                {
                    unsigned off = (unsigned)((m0 + a_lane_row) * 128 + k0 * 32 + a_lane_kb);
                    LDSM4(a0, a1, a2, a3, Abase + SWZ128(off));
                }
#pragma unroll
                for (int g = 0; g < 4; g++) {
                    uint32_t b0, b1, b2, b3;
                    int n0 = g * 16;
                    unsigned off = (unsigned)((n0 + b_lane_nr) * 128 + k0 * 32 + b_lane_kb);
                    LDSM4(b0, b1, b2, b3, Bbase + SWZ128(off));
                    MMA16816(acc[2 * g],     a0, a1, a2, a3, b0, b1);
                    MMA16816(acc[2 * g + 1], a0, a1, a2, a3, b2, b3);
                }
            }
        }
    }

    int rquad = lane >> 2;
    int r_lo = row0 + m0 + rquad, r_hi = r_lo + 8;
#pragma unroll
    for (int tile = 0; tile < 8; tile++) {
        int n_ = tile * 8 + (lane & 3) * 2;
        float2 vb = *reinterpret_cast<const float2*>(&bm[n_]);
        if (r_lo < NN) {
            float2 f = *reinterpret_cast<const float2*>(&g_feat[(size_t)r_lo * 64 + n_]);
            float v0 = acc[tile][0] + vb.x + f.x;
            float v1 = acc[tile][1] + vb.y + f.y;
            *reinterpret_cast<float2*>(&g_feat[(size_t)r_lo * 64 + n_]) = make_float2(v0, v1);
            *reinterpret_cast<float2*>(&out[(size_t)r_lo * OUTW + outbase + n_]) =
                make_float2(v0, v1);
        }
        if (r_hi < NN) {
            float2 f = *reinterpret_cast<const float2*>(&g_feat[(size_t)r_hi * 64 + n_]);
            float v0 = acc[tile][2] + vb.x + f.x;
            float v1 = acc[tile][3] + vb.y + f.y;
            *reinterpret_cast<float2*>(&g_feat[(size_t)r_hi * 64 + n_]) = make_float2(v0, v1);
            *reinterpret_cast<float2*>(&out[(size_t)r_hi * OUTW + outbase + n_]) =
                make_float2(v0, v1);
        }
    }
}

// ---------------- launch ----------------
extern "C" void kernel_launch(void* const* d_in, const int* in_sizes, int n_in,
                              void* d_out, int out_size) {
    const float* node_feat = (const float*)d_in[0];
    const float* edge_feat = (const float*)d_in[1];
    const int*   src       = (const int*)d_in[2];
    const int*   dst       = (const int*)d_in[3];
    const float* W_embed   = (const float*)d_in[4];
    const float* b_embed   = (const float*)d_in[5];
    const float* W_ni      = (const float*)d_in[6];
    const float* W_nj      = (const float*)d_in[7];
    const float* W_fij     = (const float*)d_in[8];
    const float* b_att     = (const float*)d_in[9];
    const float* attn      = (const float*)d_in[10];
    const float* W_node    = (const float*)d_in[11];
    const float* W_mlp     = (const float*)d_in[12];
    const float* b_mlp     = (const float*)d_in[13];
    float* out = (float*)d_out;

    cudaFuncSetAttribute(k_edge_mma, cudaFuncAttributeMaxDynamicSharedMemorySize,
                         SM_EDGE_TOTAL);
    cudaFuncSetAttribute(k_nodegemm_mma, cudaFuncAttributeMaxDynamicSharedMemorySize,
                         SMN_TOTAL);
    cudaFuncSetAttribute(k_mlp_mma, cudaFuncAttributeMaxDynamicSharedMemorySize,
                         SMM_TOTAL);

    // CSR by dst (+ perm-order src/dst); scan also seeds cursor
    k_zero_cursor<<<(NN + 255) / 256, 256>>>();
    k_degree<<<(EE + 255) / 256, 256>>>(dst);
    k_scan<<<1, 1024>>>();
    k_scatter<<<(EE + 255) / 256, 256>>>(src, dst);

    // preps
    k_prep_edge<<<(EE * 8 + 255) / 256, 256>>>(edge_feat);
    k_prepw<<<512, 256>>>(W_fij, W_ni, W_nj, W_node);
    k_prepw_mlp<<<128, 256>>>(W_mlp);

    // embed (+ raw feature copy)
    k_embed<<<NN / 4, 256>>>(node_feat, W_embed, b_embed, out);

    for (int L = 0; L < 2; L++) {
        const float* ba = b_att + L * 256;
        const float* at = attn  + L * 256;
        const float* bm = b_mlp + L * 64;

        dim3 ng(NPAD / 128, 3);
        k_nodegemm_mma<<<ng, 256, SMN_TOTAL>>>(L);
        k_edge_mma<<<EE / 128, 256, SM_EDGE_TOTAL>>>(L, ba, at);
        k_aggregate<<<NN / 8, 256>>>();
        k_mlp_mma<<<NPAD / 128, 256, SMM_TOTAL>>>(L, bm, out, 80 + 64 * L);
    }
}

// round 17
// speedup vs baseline: 1.5678x; 1.0509x over previous
#include <cuda_runtime.h>
#include <cuda_bf16.h>
#include <cstdint>

// Problem constants
#define NN    20000
#define EE    320000
#define NPAD  20096        // 157 * 128
#define OUTW  208          // 16 + 3*64

#define SWZ128(b) ((b) ^ (((b) >> 3) & 0x70))

// ---- warp-level tensor core primitives (arch-generic PTX, compiles for sm_103) ----
#define LDSM4(r0, r1, r2, r3, addr) \
    asm volatile("ldmatrix.sync.aligned.m8n8.x4.shared.b16 {%0,%1,%2,%3}, [%4];" \
        : "=r"(r0), "=r"(r1), "=r"(r2), "=r"(r3) : "r"(addr))

#define MMA16816(d, a0, a1, a2, a3, b0, b1) \
    asm volatile("mma.sync.aligned.m16n8k16.row.col.f32.bf16.bf16.f32 " \
        "{%0,%1,%2,%3}, {%4,%5,%6,%7}, {%8,%9}, {%0,%1,%2,%3};" \
        : "+f"((d)[0]), "+f"((d)[1]), "+f"((d)[2]), "+f"((d)[3]) \
        : "r"(a0), "r"(a1), "r"(a2), "r"(a3), "r"(b0), "r"(b1))

__device__ __forceinline__ uint32_t smem_u32(const void* p) {
    uint32_t a;
    asm("{ .reg .u64 t; cvta.to.shared.u64 t, %1; cvt.u32.u64 %0, t; }"
        : "=r"(a) : "l"(p));
    return a;
}

// packed bf16x2 convert: lo half = x, hi half = y
__device__ __forceinline__ uint32_t cvt_bf2(float x, float y) {
    uint32_t r;
    asm("cvt.rn.bf16x2.f32 %0, %1, %2;" : "=r"(r) : "f"(y), "f"(x));
    return r;
}
__device__ __forceinline__ void split2(float x, float y, uint32_t& h, uint32_t& l) {
    h = cvt_bf2(x, y);
    float hx = __uint_as_float(h << 16);
    float hy = __uint_as_float(h & 0xffff0000u);
    l = cvt_bf2(x - hx, y - hy);
}

// ---------------- scratch (device globals; no allocation) ----------------
__device__ float g_feat[NPAD * 64];
__device__ float g_cat[NPAD * 768];          // [f_ni | f_nj | hn]
__device__ float g_elog[EE * 4];             // PERM order
__device__ float g_agg[NPAD * 256];
__device__ int   g_off[NN + 1];
__device__ int   g_cursor[NN];
__device__ int   g_perm[EE];
__device__ int   g_psrc[EE];
__device__ int   g_pdst[EE];
__device__ __nv_bfloat16 g_ehi[EE * 64];
__device__ __nv_bfloat16 g_elo[EE * 64];
// W^T blobs: [layer][mat: fij,ni,nj,node][hi/lo] each 256x64 swizzled
__device__ __nv_bfloat16 g_wb[2 * 4 * 2 * 16384];
// W_mlp^T blobs: [layer][kchunk 0..3][hi/lo] each 64 rows x 64 K swizzled
__device__ __nv_bfloat16 g_wmlp[2 * 4 * 2 * 4096];

// ---------------- CSR build ----------------
__global__ void k_zero_cursor() {
    int i = blockIdx.x * blockDim.x + threadIdx.x;
    if (i < NN) g_cursor[i] = 0;
}
__global__ void k_degree(const int* __restrict__ dst) {
    int e = blockIdx.x * blockDim.x + threadIdx.x;
    if (e < EE) atomicAdd(&g_cursor[dst[e]], 1);
}
// shuffle-based scan: thread t owns chunk [20t, 20t+20). 3 barriers total.
// writes g_off (inclusive, shifted by 1) and g_cursor (exclusive prefix).
#define SCHUNK 20
__global__ void k_scan() {
    __shared__ int warp_sums[32];
    int t = threadIdx.x;
    int lane = t & 31, w = t >> 5;
    int base = t * SCHUNK;
    int vals[SCHUNK];
    int sum = 0;
#pragma unroll
    for (int i = 0; i < SCHUNK; i++) {
        int idx = base + i;
        int v = (idx < NN) ? g_cursor[idx] : 0;
        vals[i] = v;
        sum += v;
    }
    // warp inclusive scan of chunk sums
    int inc = sum;
#pragma unroll
    for (int o = 1; o < 32; o <<= 1) {
        int v = __shfl_up_sync(0xffffffffu, inc, o);
        if (lane >= o) inc += v;
    }
    if (lane == 31) warp_sums[w] = inc;
    __syncthreads();
    if (w == 0) {
        int v = warp_sums[lane];
        int s = v;
#pragma unroll
        for (int o = 1; o < 32; o <<= 1) {
            int x = __shfl_up_sync(0xffffffffu, s, o);
            if (lane >= o) s += x;
        }
        warp_sums[lane] = s - v;   // exclusive warp base
    }
    __syncthreads();
    int run = warp_sums[w] + (inc - sum);   // exclusive prefix of this chunk
#pragma unroll
    for (int i = 0; i < SCHUNK; i++) {
        int idx = base + i;
        if (idx < NN) {
            g_cursor[idx] = run;            // exclusive (scatter cursor)
            run += vals[i];
            g_off[idx + 1] = run;           // inclusive -> offsets
        }
    }
    if (t == 0) g_off[0] = 0;
}
__global__ void k_scatter(const int* __restrict__ src, const int* __restrict__ dst) {
    int e = blockIdx.x * blockDim.x + threadIdx.x;
    if (e < EE) {
        int d = dst[e];
        int p = atomicAdd(&g_cursor[d], 1);
        g_perm[p] = e;
        g_psrc[p] = src[e];
        g_pdst[p] = d;
    }
}

// ---------------- embed (+ raw feature copy, cols 0..15) ----------------
__global__ void k_embed(const float* __restrict__ nf,
                        const float* __restrict__ W, const float* __restrict__ b,
                        float* __restrict__ out) {
    __shared__ float sW[16 * 64];
    int tid = threadIdx.x;
#pragma unroll
    for (int i = 0; i < 4; i++) sW[tid + i * 256] = W[tid + i * 256];
    __syncthreads();
    int n = blockIdx.x * 4 + (tid >> 6);
    int c = tid & 63;
    if (n < NN) {
        float acc = b[c];
        const float* r = nf + n * 16;
#pragma unroll
        for (int k = 0; k < 16; k++) acc += r[k] * sW[k * 64 + c];
        g_feat[n * 64 + c] = acc;
        out[n * OUTW + 16 + c] = acc;
        if (c < 16) out[n * OUTW + c] = r[c];   // raw node features
    }
}

// ---------------- prep: edge_feat bf16 split, pre-swizzled, PERM order ----------------
__global__ void k_prep_edge(const float* __restrict__ ef) {
    int idx = blockIdx.x * 256 + threadIdx.x;
    if (idx >= EE * 8) return;
    int p = idx >> 3, q = idx & 7;
    int e = g_perm[p];
    const float* ep = ef + (size_t)e * 64 + q * 8;
    float4 a = *reinterpret_cast<const float4*>(ep);
    float4 b = *reinterpret_cast<const float4*>(ep + 4);
    uint4 H, L;
    split2(a.x, a.y, H.x, L.x);
    split2(a.z, a.w, H.y, L.y);
    split2(b.x, b.y, H.z, L.z);
    split2(b.z, b.w, H.w, L.w);
    unsigned sw = SWZ128((unsigned)((p & 127) * 128 + q * 16));
    size_t byte_base = (size_t)(p >> 7) * 16384;
    *reinterpret_cast<uint4*>(reinterpret_cast<char*>(g_ehi) + byte_base + sw) = H;
    *reinterpret_cast<uint4*>(reinterpret_cast<char*>(g_elo) + byte_base + sw) = L;
}

// ---------------- prep: W^T blobs (fij, ni, nj, node) ----------------
__global__ void k_prepw(const float* __restrict__ Wfij, const float* __restrict__ Wni,
                        const float* __restrict__ Wnj, const float* __restrict__ Wnode) {
    int idx = blockIdx.x * 256 + threadIdx.x;   // 131072
    if (idx >= 131072) return;
    int Lr = idx >> 16;
    int rem = idx & 65535;
    int mat = rem >> 14;
    int t = rem & 16383;
    int r = t >> 6, c = t & 63;
    const float* W = (mat == 0) ? Wfij : (mat == 1) ? Wni : (mat == 2) ? Wnj : Wnode;
    float v = W[Lr * 16384 + c * 256 + r];
    __nv_bfloat16 h = __float2bfloat16(v);
    __nv_bfloat16 l = __float2bfloat16(v - __bfloat162float(h));
    unsigned sw = SWZ128((unsigned)(r * 128 + c * 2)) >> 1;
    g_wb[(size_t)((Lr * 4 + mat) * 2 + 0) * 16384 + sw] = h;
    g_wb[(size_t)((Lr * 4 + mat) * 2 + 1) * 16384 + sw] = l;
}

// ---------------- prep: W_mlp^T blobs ----------------
__global__ void k_prepw_mlp(const float* __restrict__ Wm) {
    int idx = blockIdx.x * 256 + threadIdx.x;   // 32768
    if (idx >= 32768) return;
    int Lr = idx >> 14;
    int rem = idx & 16383;
    int c = rem >> 12;
    int t = rem & 4095;
    int n = t >> 6, kk = t & 63;
    float v = Wm[Lr * 16384 + (c * 64 + kk) * 64 + n];
    __nv_bfloat16 h = __float2bfloat16(v);
    __nv_bfloat16 l = __float2bfloat16(v - __bfloat162float(h));
    unsigned sw = SWZ128((unsigned)(n * 128 + kk * 2)) >> 1;
    g_wmlp[(size_t)((Lr * 4 + c) * 2 + 0) * 4096 + sw] = h;
    g_wmlp[(size_t)((Lr * 4 + c) * 2 + 1) * 4096 + sw] = l;
}

// ---------------- shared HMMA core: one m16 sub of a 128x256 block ----------------
// LDSM-sharing version: per k0, A hi/lo fragments loaded once; Bhi tiles read
// once and used for both Ahi*Bhi and Alo*Bhi; then Blo sweep reuses Ahi.
// 18 LDSM per k0 vs 27 in the naive 3-pass form.
__device__ __forceinline__ void mma_sub_128x256(
    uint32_t sb32, uint32_t ahi, uint32_t alo, uint32_t bhi, uint32_t blo,
    int m0, int cg, int lane, float (&acc)[16][4]) {
    int a_lane_row = lane & 15;
    int a_lane_kb  = (lane >> 4) * 16;
    int b_lane_nr  = (lane & 7) + (lane >> 4) * 8;
    int b_lane_kb  = ((lane >> 3) & 1) * 16;
#pragma unroll
    for (int t = 0; t < 16; t++)
#pragma unroll
        for (int q = 0; q < 4; q++) acc[t][q] = 0.f;
#pragma unroll
    for (int k0 = 0; k0 < 4; k0++) {
        uint32_t ah0, ah1, ah2, ah3, al0, al1, al2, al3;
        {
            unsigned aoff = SWZ128((unsigned)((m0 + a_lane_row) * 128 + k0 * 32 + a_lane_kb));
            LDSM4(ah0, ah1, ah2, ah3, sb32 + ahi + aoff);
            LDSM4(al0, al1, al2, al3, sb32 + alo + aoff);
        }
#pragma unroll
        for (int g = 0; g < 8; g++) {
            uint32_t b0, b1, b2, b3;
            int n0 = cg * 128 + g * 16;
            unsigned off = SWZ128((unsigned)((n0 + b_lane_nr) * 128 + k0 * 32 + b_lane_kb));
            LDSM4(b0, b1, b2, b3, sb32 + bhi + off);
            MMA16816(acc[2 * g],     ah0, ah1, ah2, ah3, b0, b1);
            MMA16816(acc[2 * g + 1], ah0, ah1, ah2, ah3, b2, b3);
            MMA16816(acc[2 * g],     al0, al1, al2, al3, b0, b1);
            MMA16816(acc[2 * g + 1], al0, al1, al2, al3, b2, b3);
        }
#pragma unroll
        for (int g = 0; g < 8; g++) {
            uint32_t b0, b1, b2, b3;
            int n0 = cg * 128 + g * 16;
            unsigned off = SWZ128((unsigned)((n0 + b_lane_nr) * 128 + k0 * 32 + b_lane_kb));
            LDSM4(b0, b1, b2, b3, sb32 + blo + off);
            MMA16816(acc[2 * g],     ah0, ah1, ah2, ah3, b0, b1);
            MMA16816(acc[2 * g + 1], ah0, ah1, ah2, ah3, b2, b3);
        }
    }
}

// ---------------- HMMA node GEMM ----------------
#define SMN_AHI 0
#define SMN_ALO 16384
#define SMN_BHI 32768
#define SMN_BLO 65536
#define SMN_TOTAL 98304

__global__ __launch_bounds__(256) void k_nodegemm_mma(int Lr) {
    extern __shared__ char smem[];
    uint32_t sb32 = smem_u32(smem);
    int tid = threadIdx.x;
    int wid = tid >> 5, lane = tid & 31;
    int row0 = blockIdx.x * 128;
    int nb = blockIdx.y;

    {
        const uint4* s1 = reinterpret_cast<const uint4*>(
            g_wb + (size_t)((Lr * 4 + nb + 1) * 2 + 0) * 16384);
        const uint4* s2 = reinterpret_cast<const uint4*>(
            g_wb + (size_t)((Lr * 4 + nb + 1) * 2 + 1) * 16384);
        uint4* d1 = reinterpret_cast<uint4*>(smem + SMN_BHI);
        uint4* d2 = reinterpret_cast<uint4*>(smem + SMN_BLO);
#pragma unroll
        for (int i = 0; i < 8; i++) {
            d1[tid + i * 256] = s1[tid + i * 256];
            d2[tid + i * 256] = s2[tid + i * 256];
        }
    }
    {
        int row = tid >> 1;
        int hc = (tid & 1) * 32;
        const float* ap = g_feat + (size_t)(row0 + row) * 64 + hc;
#pragma unroll
        for (int q = 0; q < 4; q++) {
            float4 va = *reinterpret_cast<const float4*>(ap + q * 8);
            float4 vb = *reinterpret_cast<const float4*>(ap + q * 8 + 4);
            uint4 H, L;
            split2(va.x, va.y, H.x, L.x);
            split2(va.z, va.w, H.y, L.y);
            split2(vb.x, vb.y, H.z, L.z);
            split2(vb.z, vb.w, H.w, L.w);
            unsigned sw = SWZ128((unsigned)(row * 128 + (hc + q * 8) * 2));
            *reinterpret_cast<uint4*>(smem + SMN_AHI + sw) = H;
            *reinterpret_cast<uint4*>(smem + SMN_ALO + sw) = L;
        }
    }
    __syncthreads();

    int rg = wid & 3;
    int cg = wid >> 2;
#pragma unroll
    for (int sub = 0; sub < 2; sub++) {
        int m0 = rg * 32 + sub * 16;
        float acc[16][4];
        mma_sub_128x256(sb32, SMN_AHI, SMN_ALO, SMN_BHI, SMN_BLO, m0, cg, lane, acc);

        int rquad = lane >> 2;
        int r_lo = row0 + m0 + rquad, r_hi = r_lo + 8;
        float* c_lo = g_cat + (size_t)r_lo * 768 + nb * 256;
        float* c_hi = g_cat + (size_t)r_hi * 768 + nb * 256;
#pragma unroll
        for (int tile = 0; tile < 16; tile++) {
            int n_ = cg * 128 + tile * 8 + (lane & 3) * 2;
            *reinterpret_cast<float2*>(c_lo + n_) = make_float2(acc[tile][0], acc[tile][1]);
            *reinterpret_cast<float2*>(c_hi + n_) = make_float2(acc[tile][2], acc[tile][3]);
        }
    }
}

// ---------------- HMMA fused edge logits (PERM order) ----------------
#define SM_SRC    0
#define SM_DST    512
#define SM_BATT   1024
#define SM_ATTN   2048
#define SM_AHI    4096
#define SM_ALO    20480
#define SM_BHI    36864
#define SM_BLO    69632
#define SM_EDGE_TOTAL 102400

__global__ __launch_bounds__(256) void k_edge_mma(
    int Lr,
    const float* __restrict__ batt,
    const float* __restrict__ attn) {
    extern __shared__ char smem[];
    uint32_t sb32 = smem_u32(smem);
    int tid = threadIdx.x;
    int wid = tid >> 5, lane = tid & 31;
    int e0 = blockIdx.x * 128;

    ((float*)(smem + SM_BATT))[tid] = batt[tid];
    ((float*)(smem + SM_ATTN))[tid] = attn[tid];
    if (tid < 128) {
        ((int*)(smem + SM_SRC))[tid] = g_psrc[e0 + tid];
        ((int*)(smem + SM_DST))[tid] = g_pdst[e0 + tid];
    }

    {
        const uint4* s1 = reinterpret_cast<const uint4*>(
            g_wb + (size_t)((Lr * 4 + 0) * 2 + 0) * 16384);
        const uint4* s2 = reinterpret_cast<const uint4*>(
            g_wb + (size_t)((Lr * 4 + 0) * 2 + 1) * 16384);
        uint4* d1 = reinterpret_cast<uint4*>(smem + SM_BHI);
        uint4* d2 = reinterpret_cast<uint4*>(smem + SM_BLO);
#pragma unroll
        for (int i = 0; i < 8; i++) {
            d1[tid + i * 256] = s1[tid + i * 256];
            d2[tid + i * 256] = s2[tid + i * 256];
        }
    }
    {
        size_t byte_base = (size_t)blockIdx.x * 16384;
        const uint4* s1 = reinterpret_cast<const uint4*>(
            reinterpret_cast<const char*>(g_ehi) + byte_base);
        const uint4* s2 = reinterpret_cast<const uint4*>(
            reinterpret_cast<const char*>(g_elo) + byte_base);
        uint4* d1 = reinterpret_cast<uint4*>(smem + SM_AHI);
        uint4* d2 = reinterpret_cast<uint4*>(smem + SM_ALO);
#pragma unroll
        for (int i = 0; i < 4; i++) {
            d1[tid + i * 256] = s1[tid + i * 256];
            d2[tid + i * 256] = s2[tid + i * 256];
        }
    }
    __syncthreads();

    const int* ssrc = (const int*)(smem + SM_SRC);
    const int* sdst = (const int*)(smem + SM_DST);
    const float* sbp = (const float*)(smem + SM_BATT);
    const float* sap = (const float*)(smem + SM_ATTN);

    int rg = wid & 3;
    int cg = wid >> 2;

#pragma unroll
    for (int sub = 0; sub < 2; sub++) {
        int m0 = rg * 32 + sub * 16;
        float acc[16][4];
        mma_sub_128x256(sb32, SM_AHI, SM_ALO, SM_BHI, SM_BLO, m0, cg, lane, acc);

        int rquad = lane >> 2;
        int r_lo = m0 + rquad, r_hi = r_lo + 8;
        const float* ni_lo = g_cat + (size_t)ssrc[r_lo] * 768;
        const float* nj_lo = g_cat + (size_t)sdst[r_lo] * 768 + 256;
        const float* ni_hi = g_cat + (size_t)ssrc[r_hi] * 768;
        const float* nj_hi = g_cat + (size_t)sdst[r_hi] * 768 + 256;

        float pr00 = 0.f, pr01 = 0.f, pr10 = 0.f, pr11 = 0.f;
#pragma unroll
        for (int tile = 0; tile < 16; tile++) {
            int n_ = cg * 128 + tile * 8 + (lane & 3) * 2;
            float2 vb = *reinterpret_cast<const float2*>(&sbp[n_]);
            float2 va = *reinterpret_cast<const float2*>(&sap[n_]);
            float2 gli = *reinterpret_cast<const float2*>(&ni_lo[n_]);
            float2 glj = *reinterpret_cast<const float2*>(&nj_lo[n_]);
            float2 ghi = *reinterpret_cast<const float2*>(&ni_hi[n_]);
            float2 ghj = *reinterpret_cast<const float2*>(&nj_hi[n_]);
            float x0 = acc[tile][0] + gli.x + glj.x + vb.x;
            float x1 = acc[tile][1] + gli.y + glj.y + vb.y;
            float y0 = acc[tile][2] + ghi.x + ghj.x + vb.x;
            float y1 = acc[tile][3] + ghi.y + ghj.y + vb.y;
            x0 = (x0 > 0.f) ? x0 : 0.2f * x0;
            x1 = (x1 > 0.f) ? x1 : 0.2f * x1;
            y0 = (y0 > 0.f) ? y0 : 0.2f * y0;
            y1 = (y1 > 0.f) ? y1 : 0.2f * y1;
            float plo = x0 * va.x + x1 * va.y;
            float phi = y0 * va.x + y1 * va.y;
            if (tile < 8) { pr00 += plo; pr10 += phi; }
            else          { pr01 += plo; pr11 += phi; }
        }
#pragma unroll
        for (int o = 1; o <= 2; o <<= 1) {
            pr00 += __shfl_xor_sync(0xffffffffu, pr00, o);
            pr01 += __shfl_xor_sync(0xffffffffu, pr01, o);
            pr10 += __shfl_xor_sync(0xffffffffu, pr10, o);
            pr11 += __shfl_xor_sync(0xffffffffu, pr11, o);
        }
        if ((lane & 3) == 0) {
            *reinterpret_cast<float2*>(&g_elog[(size_t)(e0 + r_lo) * 4 + cg * 2]) =
                make_float2(pr00, pr01);
            *reinterpret_cast<float2*>(&g_elog[(size_t)(e0 + r_hi) * 4 + cg * 2]) =
                make_float2(pr10, pr11);
        }
    }
}

// ---------------- softmax + aggregation (linear CSR) ----------------
__global__ __launch_bounds__(256) void k_aggregate() {
    __shared__ float sw[8][32][4];
    __shared__ int   se[8][32];
    int tid = threadIdx.x;
    int w = tid >> 5, lane = tid & 31;
    int node = blockIdx.x * 8 + w;
    if (node >= NN) return;
    int lo = g_off[node], hi = g_off[node + 1];

    const float4* elog4 = reinterpret_cast<const float4*>(g_elog);

    float4 mx = make_float4(-1e30f, -1e30f, -1e30f, -1e30f);
    for (int i = lo + lane; i < hi; i += 32) {
        float4 v = elog4[i];
        mx.x = fmaxf(mx.x, v.x); mx.y = fmaxf(mx.y, v.y);
        mx.z = fmaxf(mx.z, v.z); mx.w = fmaxf(mx.w, v.w);
    }
#pragma unroll
    for (int o = 16; o; o >>= 1) {
        mx.x = fmaxf(mx.x, __shfl_xor_sync(0xffffffffu, mx.x, o));
        mx.y = fmaxf(mx.y, __shfl_xor_sync(0xffffffffu, mx.y, o));
        mx.z = fmaxf(mx.z, __shfl_xor_sync(0xffffffffu, mx.z, o));
        mx.w = fmaxf(mx.w, __shfl_xor_sync(0xffffffffu, mx.w, o));
    }

    float4 z = make_float4(0.f, 0.f, 0.f, 0.f);
    for (int i = lo + lane; i < hi; i += 32) {
        float4 v = elog4[i];
        z.x += __expf(v.x - mx.x); z.y += __expf(v.y - mx.y);
        z.z += __expf(v.z - mx.z); z.w += __expf(v.w - mx.w);
    }
#pragma unroll
    for (int o = 16; o; o >>= 1) {
        z.x += __shfl_xor_sync(0xffffffffu, z.x, o);
        z.y += __shfl_xor_sync(0xffffffffu, z.y, o);
        z.z += __shfl_xor_sync(0xffffffffu, z.z, o);
        z.w += __shfl_xor_sync(0xffffffffu, z.w, o);
    }
    float4 zi;
    zi.x = (z.x > 0.f) ? 1.f / z.x : 0.f;
    zi.y = (z.y > 0.f) ? 1.f / z.y : 0.f;
    zi.z = (z.z > 0.f) ? 1.f / z.z : 0.f;
    zi.w = (z.w > 0.f) ? 1.f / z.w : 0.f;

    float4 a0 = make_float4(0.f, 0.f, 0.f, 0.f);
    float4 a1 = make_float4(0.f, 0.f, 0.f, 0.f);
    int hd = lane >> 3;

    for (int c0 = lo; c0 < hi; c0 += 32) {
        int i = c0 + lane;
        if (i < hi) {
            float4 v = elog4[i];
            sw[w][lane][0] = __expf(v.x - mx.x) * zi.x;
            sw[w][lane][1] = __expf(v.y - mx.y) * zi.y;
            sw[w][lane][2] = __expf(v.z - mx.z) * zi.z;
            sw[w][lane][3] = __expf(v.w - mx.w) * zi.w;
            se[w][lane] = g_psrc[i];
        }
        __syncwarp();
        int cnt = min(32, hi - c0);
        int u = 0;
        for (; u + 2 <= cnt; u += 2) {
            float wg0 = sw[w][u][hd];
            float wg1 = sw[w][u + 1][hd];
            const float4* p0 = reinterpret_cast<const float4*>(
                g_cat + (size_t)se[w][u] * 768 + 512);
            const float4* p1 = reinterpret_cast<const float4*>(
                g_cat + (size_t)se[w][u + 1] * 768 + 512);
            float4 h00 = p0[lane * 2], h01 = p0[lane * 2 + 1];
            float4 h10 = p1[lane * 2], h11 = p1[lane * 2 + 1];
            a0.x += h00.x * wg0; a0.y += h00.y * wg0; a0.z += h00.z * wg0; a0.w += h00.w * wg0;
            a1.x += h01.x * wg0; a1.y += h01.y * wg0; a1.z += h01.z * wg0; a1.w += h01.w * wg0;
            a0.x += h10.x * wg1; a0.y += h10.y * wg1; a0.z += h10.z * wg1; a0.w += h10.w * wg1;
            a1.x += h11.x * wg1; a1.y += h11.y * wg1; a1.z += h11.z * wg1; a1.w += h11.w * wg1;
        }
        if (u < cnt) {
            float wgt = sw[w][u][hd];
            const float4* p0 = reinterpret_cast<const float4*>(
                g_cat + (size_t)se[w][u] * 768 + 512);
            float4 h0 = p0[lane * 2], h1 = p0[lane * 2 + 1];
            a0.x += h0.x * wgt; a0.y += h0.y * wgt; a0.z += h0.z * wgt; a0.w += h0.w * wgt;
            a1.x += h1.x * wgt; a1.y += h1.y * wgt; a1.z += h1.z * wgt; a1.w += h1.w * wgt;
        }
        __syncwarp();
    }
    float4* outp = reinterpret_cast<float4*>(g_agg + (size_t)node * 256 + lane * 8);
    outp[0] = a0;
    outp[1] = a1;
}

// ---------------- HMMA MLP + residual ----------------
#define SMM_AHI 0
#define SMM_ALO 16384
#define SMM_BHI 32768
#define SMM_BLO 40960
#define SMM_TOTAL 49152

__global__ __launch_bounds__(256) void k_mlp_mma(
    int Lr, const float* __restrict__ bm,
    float* __restrict__ out, int outbase) {
    extern __shared__ char smem[];
    uint32_t sb32 = smem_u32(smem);
    int tid = threadIdx.x;
    int wid = tid >> 5, lane = tid & 31;
    int row0 = blockIdx.x * 128;

    int a_lane_row = lane & 15;
    int a_lane_kb  = (lane >> 4) * 16;
    int b_lane_nr  = (lane & 7) + (lane >> 4) * 8;
    int b_lane_kb  = ((lane >> 3) & 1) * 16;
    int m0 = wid * 16;

    float acc[8][4];
#pragma unroll
    for (int t = 0; t < 8; t++)
#pragma unroll
        for (int q = 0; q < 4; q++) acc[t][q] = 0.f;

    for (int ch = 0; ch < 4; ch++) {
        __syncthreads();
        {
            const uint4* s1 = reinterpret_cast<const uint4*>(
                g_wmlp + (size_t)((Lr * 4 + ch) * 2 + 0) * 4096);
            const uint4* s2 = reinterpret_cast<const uint4*>(
                g_wmlp + (size_t)((Lr * 4 + ch) * 2 + 1) * 4096);
            uint4* d1 = reinterpret_cast<uint4*>(smem + SMM_BHI);
            uint4* d2 = reinterpret_cast<uint4*>(smem + SMM_BLO);
#pragma unroll
            for (int i = 0; i < 2; i++) {
                d1[tid + i * 256] = s1[tid + i * 256];
                d2[tid + i * 256] = s2[tid + i * 256];
            }
        }
        {
            int row = tid >> 1;
            int hc = (tid & 1) * 32;
            const float* ap = g_agg + (size_t)(row0 + row) * 256 + ch * 64 + hc;
#pragma unroll
            for (int q = 0; q < 4; q++) {
                float4 va = *reinterpret_cast<const float4*>(ap + q * 8);
                float4 vb = *reinterpret_cast<const float4*>(ap + q * 8 + 4);
                uint4 H, L;
                split2(va.x, va.y, H.x, L.x);
                split2(va.z, va.w, H.y, L.y);
                split2(vb.x, vb.y, H.z, L.z);
                split2(vb.z, vb.w, H.w, L.w);
                unsigned sw = SWZ128((unsigned)(row * 128 + (hc + q * 8) * 2));
                *reinterpret_cast<uint4*>(smem + SMM_AHI + sw) = H;
                *reinterpret_cast<uint4*>(smem + SMM_ALO + sw) = L;
            }
        }
        __syncthreads();

#pragma unroll
        for (int k0 = 0; k0 < 4; k0++) {
            uint32_t ah0, ah1, ah2, ah3, al0, al1, al2, al3;
            {
                unsigned aoff = SWZ128((unsigned)((m0 + a_lane_row) * 128 + k0 * 32 + a_lane_kb));
                LDSM4(ah0, ah1, ah2, ah3, sb32 + SMM_AHI + aoff);
                LDSM4(al0, al1, al2, al3, sb32 + SMM_ALO + aoff);
            }
#pragma unroll
            for (int g = 0; g < 4; g++) {
                uint32_t b0, b1, b2, b3;
                int n0 = g * 16;
                unsigned off = SWZ128((unsigned)((n0 + b_lane_nr) * 128 + k0 * 32 + b_lane_kb));
                LDSM4(b0, b1, b2, b3, sb32 + SMM_BHI + off);
                MMA16816(acc[2 * g],     ah0, ah1, ah2, ah3, b0, b1);
                MMA16816(acc[2 * g + 1], ah0, ah1, ah2, ah3, b2, b3);
                MMA16816(acc[2 * g],     al0, al1, al2, al3, b0, b1);
                MMA16816(acc[2 * g + 1], al0, al1, al2, al3, b2, b3);
            }
#pragma unroll
            for (int g = 0; g < 4; g++) {
                uint32_t b0, b1, b2, b3;
                int n0 = g * 16;
                unsigned off = SWZ128((unsigned)((n0 + b_lane_nr) * 128 + k0 * 32 + b_lane_kb));
                LDSM4(b0, b1, b2, b3, sb32 + SMM_BLO + off);
                MMA16816(acc[2 * g],     ah0, ah1, ah2, ah3, b0, b1);
                MMA16816(acc[2 * g + 1], ah0, ah1, ah2, ah3, b2, b3);
            }
        }
    }

    int rquad = lane >> 2;
    int r_lo = row0 + m0 + rquad, r_hi = r_lo + 8;
#pragma unroll
    for (int tile = 0; tile < 8; tile++) {
        int n_ = tile * 8 + (lane & 3) * 2;
        float2 vb = *reinterpret_cast<const float2*>(&bm[n_]);
        if (r_lo < NN) {
            float2 f = *reinterpret_cast<const float2*>(&g_feat[(size_t)r_lo * 64 + n_]);
            float v0 = acc[tile][0] + vb.x + f.x;
            float v1 = acc[tile][1] + vb.y + f.y;
            *reinterpret_cast<float2*>(&g_feat[(size_t)r_lo * 64 + n_]) = make_float2(v0, v1);
            *reinterpret_cast<float2*>(&out[(size_t)r_lo * OUTW + outbase + n_]) =
                make_float2(v0, v1);
        }
        if (r_hi < NN) {
            float2 f = *reinterpret_cast<const float2*>(&g_feat[(size_t)r_hi * 64 + n_]);
            float v0 = acc[tile][2] + vb.x + f.x;
            float v1 = acc[tile][3] + vb.y + f.y;
            *reinterpret_cast<float2*>(&g_feat[(size_t)r_hi * 64 + n_]) = make_float2(v0, v1);
            *reinterpret_cast<float2*>(&out[(size_t)r_hi * OUTW + outbase + n_]) =
                make_float2(v0, v1);
        }
    }
}

// ---------------- launch ----------------
extern "C" void kernel_launch(void* const* d_in, const int* in_sizes, int n_in,
                              void* d_out, int out_size) {
    const float* node_feat = (const float*)d_in[0];
    const float* edge_feat = (const float*)d_in[1];
    const int*   src       = (const int*)d_in[2];
    const int*   dst       = (const int*)d_in[3];
    const float* W_embed   = (const float*)d_in[4];
    const float* b_embed   = (const float*)d_in[5];
    const float* W_ni      = (const float*)d_in[6];
    const float* W_nj      = (const float*)d_in[7];
    const float* W_fij     = (const float*)d_in[8];
    const float* b_att     = (const float*)d_in[9];
    const float* attn      = (const float*)d_in[10];
    const float* W_node    = (const float*)d_in[11];
    const float* W_mlp     = (const float*)d_in[12];
    const float* b_mlp     = (const float*)d_in[13];
    float* out = (float*)d_out;

    cudaFuncSetAttribute(k_edge_mma, cudaFuncAttributeMaxDynamicSharedMemorySize,
                         SM_EDGE_TOTAL);
    cudaFuncSetAttribute(k_nodegemm_mma, cudaFuncAttributeMaxDynamicSharedMemorySize,
                         SMN_TOTAL);
    cudaFuncSetAttribute(k_mlp_mma, cudaFuncAttributeMaxDynamicSharedMemorySize,
                         SMM_TOTAL);

    // CSR by dst (+ perm-order src/dst); scan also seeds cursor
    k_zero_cursor<<<(NN + 255) / 256, 256>>>();
    k_degree<<<(EE + 255) / 256, 256>>>(dst);
    k_scan<<<1, 1024>>>();
    k_scatter<<<(EE + 255) / 256, 256>>>(src, dst);

    // preps
    k_prep_edge<<<(EE * 8 + 255) / 256, 256>>>(edge_feat);
    k_prepw<<<512, 256>>>(W_fij, W_ni, W_nj, W_node);
    k_prepw_mlp<<<128, 256>>>(W_mlp);

    // embed (+ raw feature copy)
    k_embed<<<NN / 4, 256>>>(node_feat, W_embed, b_embed, out);

    for (int L = 0; L < 2; L++) {
        const float* ba = b_att + L * 256;
        const float* at = attn  + L * 256;
        const float* bm = b_mlp + L * 64;

        dim3 ng(NPAD / 128, 3);
        k_nodegemm_mma<<<ng, 256, SMN_TOTAL>>>(L);
        k_edge_mma<<<EE / 128, 256, SM_EDGE_TOTAL>>>(L, ba, at);
        k_aggregate<<<NN / 8, 256>>>();
        k_mlp_mma<<<NPAD / 128, 256, SMM_TOTAL>>>(L, bm, out, 80 + 64 * L);
    }
}